// round 7
// baseline (speedup 1.0000x reference)
#include <cuda_runtime.h>
#include <math.h>
#include <stdint.h>

#define G   16
#define C   256
#define NP  5
#define NN  4096   // 64*64
#define H   1024
#define W   1024
#define STAGES 10

// ---------------- scratch (device globals; no allocations allowed) ----------
__device__ float g_msmall[G][NN];
__device__ float g_mu[G][C][NP];          // prototypes (normalized), f32
__device__ float g_munum[G][C][NP];       // mu numerator (pre-l2norm)
__device__ float g_z[G][NP][NN];          // softmax z, k-planar
__device__ float g_zn[G][NP][NN];         // z / (1e-6 + colsum)
__device__ float g_sim[G][NP][NN];        // final similarity maps
__device__ float g_csum_part[G][16][NP];  // colsum partials (fixed order)
__device__ unsigned long long g_best[G][NP];
__device__ int g_visible[G];

// ---------------- helpers ---------------------------------------------------
__device__ __forceinline__ unsigned long long pack_key(float v, unsigned idx) {
    unsigned u = __float_as_uint(v);
    u = (u & 0x80000000u) ? ~u : (u | 0x80000000u);   // order-preserving
    return (((unsigned long long)u) << 32) | (0xFFFFFFFFu - idx);
}

// ---------------- m_small (exact: frac = 0.5 both dims, values k/4) ---------
__global__ __launch_bounds__(256)
void k_msmall(const int* __restrict__ fg) {
    int b = blockIdx.x;
    int g = b >> 4;
    int n = ((b & 15) << 8) + threadIdx.x;
    int y = n >> 6, x = n & 63;
    const int* p = fg + ((size_t)g * H + (y * 16 + 7)) * W + (x * 16 + 7);
    int s = (p[0] != 0) + (p[1] != 0) + (p[W] != 0) + (p[W + 1] != 0);
    g_msmall[g][n] = 0.25f * (float)s;
}

// ---------------- init: mu0 = mu / (1e-6 + l2norm), sequential c ------------
__global__ __launch_bounds__(256)
void k_init(const float* __restrict__ mu_in) {
    int c = threadIdx.x;
    __shared__ float sv[C][NP];
    __shared__ float rn[NP];
#pragma unroll
    for (int k = 0; k < NP; k++) sv[c][k] = mu_in[c * NP + k];
    __syncthreads();
    if (c < NP) {
        float s2 = 0.0f;
        for (int cc = 0; cc < C; cc++) {
            float q = __fmul_rn(sv[cc][c], sv[cc][c]);
            s2 = __fadd_rn(s2, q);
        }
        rn[c] = __fadd_rn(1e-6f, sqrtf(s2));
    }
    __syncthreads();
#pragma unroll
    for (int k = 0; k < NP; k++) {
        float nv = __fdiv_rn(sv[c][k], rn[k]);
        for (int g = 0; g < G; g++) g_mu[g][c][k] = nv;
    }
    if (c < G * NP) ((unsigned long long*)g_best)[c] = 0ull;
    if (c < G) g_visible[c] = 0;
}

// ---------------- logits: a = x^T mu, x = fl(ms*f), sequential-c FMA --------
// grid = G*16 x 256; one n per thread. simmode: writes sim instead.
__global__ __launch_bounds__(256)
void k_logits(const float* __restrict__ feat, int simmode) {
    int b = blockIdx.x;
    int g = b >> 4;
    int n = ((b & 15) << 8) + threadIdx.x;

    __shared__ float smu[C * NP];
    {
        const float* mug = (const float*)g_mu[g];
        for (int i = threadIdx.x; i < C * NP; i += 256) smu[i] = mug[i];
    }
    __syncthreads();

    float ms = g_msmall[g][n];
    float a[NP];
#pragma unroll
    for (int k = 0; k < NP; k++) a[k] = 0.0f;

    const float* fb = feat + n;
#pragma unroll 8
    for (int c = 0; c < C; c++) {                       // ascending c
        float x = __fmul_rn(ms, fb[(size_t)c * NN]);    // materialized x element
        const float* m = &smu[c * NP];
#pragma unroll
        for (int k = 0; k < NP; k++) a[k] = __fmaf_rn(x, m[k], a[k]);
    }

    if (simmode) {
#pragma unroll
        for (int k = 0; k < NP; k++) g_sim[g][k][n] = a[k];
        return;
    }

    float s[NP];
#pragma unroll
    for (int k = 0; k < NP; k++) s[k] = __fmul_rn(20.0f, a[k]);
    float mx = s[0];
#pragma unroll
    for (int k = 1; k < NP; k++) mx = fmaxf(mx, s[k]);
    float e[NP];
#pragma unroll
    for (int k = 0; k < NP; k++) e[k] = expf(__fadd_rn(s[k], -mx));
    float sum = e[0];
#pragma unroll
    for (int k = 1; k < NP; k++) sum = __fadd_rn(sum, e[k]);

    float zs[NP];
#pragma unroll
    for (int k = 0; k < NP; k++) {
        float z = __fdiv_rn(e[k], sum);                 // e / sum (IEEE divide)
        g_z[g][k][n] = z;
        zs[k] = z;
    }

    // deterministic colsum partials: shfl tree -> fixed 8-warp sum
    __shared__ float wpart[8][NP];
    int warp = threadIdx.x >> 5, lane = threadIdx.x & 31;
#pragma unroll
    for (int k = 0; k < NP; k++) {
        float t = zs[k];
        for (int o = 16; o > 0; o >>= 1) t += __shfl_down_sync(0xffffffffu, t, o);
        if (lane == 0) wpart[warp][k] = t;
    }
    __syncthreads();
    if (threadIdx.x < NP) {
        float ssum = 0.0f;
#pragma unroll
        for (int w = 0; w < 8; w++) ssum = __fadd_rn(ssum, wpart[w][threadIdx.x]);
        g_csum_part[g][b & 15][threadIdx.x] = ssum;
    }
}

// ---------------- zn = z / (1e-6 + colsum) ----------------------------------
__global__ __launch_bounds__(256)
void k_zn() {
    int b = blockIdx.x;
    int g = b >> 4;
    int n = ((b & 15) << 8) + threadIdx.x;
    __shared__ float den[NP];
    if (threadIdx.x < NP) {
        float s = 0.0f;
#pragma unroll
        for (int j = 0; j < 16; j++) s = __fadd_rn(s, g_csum_part[g][j][threadIdx.x]);
        den[threadIdx.x] = __fadd_rn(1e-6f, s);
    }
    __syncthreads();
#pragma unroll
    for (int k = 0; k < NP; k++)
        g_zn[g][k][n] = __fdiv_rn(g_z[g][k][n], den[k]);
}

// ---------------- mu numerator: warp per (g,c), lane-strided float4 ---------
// grid = G*32 x 256 (8 warps = 8 channels per block). R2's correlating pattern.
__global__ __launch_bounds__(256)
void k_mu(const float* __restrict__ feat) {
    int b = blockIdx.x;
    int g = b >> 5;
    int warp = threadIdx.x >> 5, lane = threadIdx.x & 31;
    int c = ((b & 31) << 3) + warp;

    const float* fr = feat + (size_t)c * NN;
    const float* mr = g_msmall[g];
    float acc[NP];
#pragma unroll
    for (int k = 0; k < NP; k++) acc[k] = 0.0f;

    for (int it = 0; it < 32; it++) {
        int n = it * 128 + lane * 4;                    // lane-strided, x4 vectorized
        float4 f4 = *(const float4*)(fr + n);
        float4 m4 = *(const float4*)(mr + n);
        float x0 = __fmul_rn(m4.x, f4.x);               // materialized x elements
        float x1 = __fmul_rn(m4.y, f4.y);
        float x2 = __fmul_rn(m4.z, f4.z);
        float x3 = __fmul_rn(m4.w, f4.w);
#pragma unroll
        for (int k = 0; k < NP; k++) {
            float4 z4 = *(const float4*)&g_zn[g][k][n];
            acc[k] = __fmaf_rn(x0, z4.x, acc[k]);
            acc[k] = __fmaf_rn(x1, z4.y, acc[k]);
            acc[k] = __fmaf_rn(x2, z4.z, acc[k]);
            acc[k] = __fmaf_rn(x3, z4.w, acc[k]);
        }
    }
#pragma unroll
    for (int k = 0; k < NP; k++)
        for (int o = 16; o > 0; o >>= 1) acc[k] += __shfl_down_sync(0xffffffffu, acc[k], o);

    if (lane == 0) {
#pragma unroll
        for (int k = 0; k < NP; k++) g_munum[g][c][k] = acc[k];
    }
}

// ---------------- l2-normalize mu: sequential-c ssq, IEEE divide ------------
__global__ __launch_bounds__(256)
void k_norm() {
    int g = blockIdx.x;
    int c = threadIdx.x;
    __shared__ float rn[NP];
    if (c < NP) {
        float s2 = 0.0f;
        for (int cc = 0; cc < C; cc++) {
            float v = g_munum[g][cc][c];
            float q = __fmul_rn(v, v);
            s2 = __fadd_rn(s2, q);
        }
        rn[c] = __fadd_rn(1e-6f, sqrtf(s2));
    }
    __syncthreads();
#pragma unroll
    for (int k = 0; k < NP; k++)
        g_mu[g][c][k] = __fdiv_rn(g_munum[g][c][k], rn[k]);
}

// ---------------- final: upsample + assign + write + reductions -------------
__global__ __launch_bounds__(256)
void k_final(const int* __restrict__ fg, float* __restrict__ out) {
    int y = blockIdx.x, g = blockIdx.y;

    __shared__ float row[NP][64];
    float sy = (y + 0.5f) * 0.0625f - 0.5f;          // exact in f32
    sy = fminf(fmaxf(sy, 0.0f), 63.0f);
    int y0 = (int)sy; int y1 = min(y0 + 1, 63); float fy = sy - (float)y0;
    float wy0 = 1.0f - fy;

    for (int i = threadIdx.x; i < NP * 64; i += 256) {
        int k = i >> 6, xs = i & 63;
        float a = g_sim[g][k][y0 * 64 + xs];
        float bb = g_sim[g][k][y1 * 64 + xs];
        row[k][xs] = __fadd_rn(__fmul_rn(a, wy0), __fmul_rn(bb, fy));
    }
    __syncthreads();

    int xb = threadIdx.x << 2;
    int4 fg4 = *(const int4*)(fg + ((size_t)g * H + y) * W + xb);
    const int* fgv4 = &fg4.x;

    unsigned long long best[NP];
#pragma unroll
    for (int k = 0; k < NP; k++) best[k] = 0ull;
    int vb = 0;
    float ov[NP][4];

#pragma unroll
    for (int j = 0; j < 4; j++) {
        int x = xb + j;
        float sx = (x + 0.5f) * 0.0625f - 0.5f;
        sx = fminf(fmaxf(sx, 0.0f), 63.0f);
        int x0 = (int)sx; int x1 = min(x0 + 1, 63); float fx = sx - (float)x0;
        float wx0 = 1.0f - fx;

        float v[NP];
#pragma unroll
        for (int k = 0; k < NP; k++)
            v[k] = __fadd_rn(__fmul_rn(row[k][x0], wx0), __fmul_rn(row[k][x1], fx));

        int bk = 0; float bv = v[0];
#pragma unroll
        for (int k = 1; k < NP; k++) if (v[k] > bv) { bv = v[k]; bk = k; }

        int isfg = (fgv4[j] != 0);
        unsigned idx = (unsigned)(y * W + x);
#pragma unroll
        for (int k = 0; k < NP; k++) {
            float o = (isfg && k == bk) ? v[k] : 0.0f;
            ov[k][j] = o;
            unsigned long long key = pack_key(o, idx);
            if (key > best[k]) best[k] = key;
        }
        if (isfg) vb |= (1 << bk);
    }

#pragma unroll
    for (int k = 0; k < NP; k++) {
        float4 w4 = make_float4(ov[k][0], ov[k][1], ov[k][2], ov[k][3]);
        *(float4*)(out + ((((size_t)g * NP + k) * H + y) * W + xb)) = w4;
    }

#pragma unroll
    for (int k = 0; k < NP; k++)
        for (int o = 16; o > 0; o >>= 1) {
            unsigned long long other = __shfl_down_sync(0xffffffffu, best[k], o);
            if (other > best[k]) best[k] = other;
        }
    for (int o = 16; o > 0; o >>= 1) vb |= __shfl_down_sync(0xffffffffu, vb, o);

    __shared__ unsigned long long sb[8][NP];
    __shared__ int sv[8];
    int warp = threadIdx.x >> 5, lane = threadIdx.x & 31;
    if (lane == 0) {
#pragma unroll
        for (int k = 0; k < NP; k++) sb[warp][k] = best[k];
        sv[warp] = vb;
    }
    __syncthreads();
    if (threadIdx.x < NP) {
        int k = threadIdx.x;
        unsigned long long m = sb[0][k];
#pragma unroll
        for (int w = 1; w < 8; w++) if (sb[w][k] > m) m = sb[w][k];
        atomicMax(&g_best[g][k], m);
    }
    if (threadIdx.x == 0) {
        int o = 0;
#pragma unroll
        for (int w = 0; w < 8; w++) o |= sv[w];
        atomicOr(&g_visible[g], o);
    }
}

// ---------------- epilogue --------------------------------------------------
__global__ __launch_bounds__(128)
void k_points(float* __restrict__ out) {
    int t = threadIdx.x;
    if (t >= G * NP) return;
    int g = t / NP, k = t % NP;
    int vis = (g_visible[g] >> k) & 1;
    unsigned idx = 0xFFFFFFFFu - (unsigned)(g_best[g][k] & 0xFFFFFFFFull);
    float px = (float)(idx & (W - 1));
    float py = (float)(idx >> 10);
    size_t P = (size_t)G * NP * H * W;
    out[P + t * 2]     = vis ? px : -0.001f;
    out[P + t * 2 + 1] = vis ? py : -0.001f;
    out[P + (size_t)G * NP * 2 + t] = (float)vis;
}

// ---------------- launch ----------------------------------------------------
extern "C" void kernel_launch(void* const* d_in, const int* in_sizes, int n_in,
                              void* d_out, int out_size) {
    const float* feature = (const float*)d_in[0];   // (256,64,64)
    const int*   fg_mask = (const int*)d_in[1];     // (16,1024,1024)
    // d_in[2] = bboxes (unused by reference)
    const float* mu_in   = (const float*)d_in[3];   // (1,256,5)
    float* out = (float*)d_out;

    k_msmall<<<G * 16, 256>>>(fg_mask);
    k_init<<<1, 256>>>(mu_in);

    for (int it = 0; it < STAGES; it++) {
        k_logits<<<G * 16, 256>>>(feature, 0);
        k_zn<<<G * 16, 256>>>();
        k_mu<<<G * 32, 256>>>(feature);
        k_norm<<<G, 256>>>();
    }
    k_logits<<<G * 16, 256>>>(feature, 1);   // sim = x^T mu_final

    k_final<<<dim3(H, G), 256>>>(fg_mask, out);
    k_points<<<1, 128>>>(out);
}